// round 15
// baseline (speedup 1.0000x reference)
#include <cuda_runtime.h>
#include <cuda_bf16.h>
#include <math.h>
#include <stdint.h>

// Problem dims
#define Tn 512
#define Bn 64
#define In 512
#define Hn 1024
#define On 512
#define Gn 4096
#define TBn (Tn*Bn)           // 32768

#define NCTA 128
#define NTHR 512

// ---- recurrence smem layout (bytes) ----
#define RWS 2064                       // W row stride (1024 bf16 + 16B pad)
#define W_LO_OFF (32*RWS)              // 66048
#define A_OFF    (2*32*RWS)            // 132096
#define A_CSTR   144                   // 64 k-bf16 (128B) + 16B pad
#define A_QB     (32*A_CSTR)           // 4608  (32 batch rows, one quarter slice)
#define A_SELB   (4*A_QB)              // 18432 (4 quarters; hi or lo)
#define A_STAGE  (2*A_SELB)            // 36864 (hi+lo)
#define GSM_OFF  (A_OFF + 2*A_STAGE)   // 205824
#define GSTR 34                        // even: float2 stays 8B-aligned
#define GSM_QB   (32*GSTR*4)           // 4352 per quarter
#define SMEM_RECUR (GSM_OFF + 4*GSM_QB) // 223232

// ---- HMMA GEMM tile config (R7-proven) ----
#define BM 128
#define BN 128
#define BK 32
#define ROWB 80
#define MATB (128*ROWB)
#define STGB (4*MATB)
#define SMEM_GEMM (2*STGB)

// Scratch (device globals)
__device__ float g_pre[(size_t)TBn * Gn];
__device__ float g_c[Bn * Hn];
__device__ unsigned g_arr[2][NCTA] = {};
__device__ unsigned g_gen[2] = {};
__device__ __nv_bfloat16 g_hhi[Bn * Hn];
__device__ __nv_bfloat16 g_hlo[Bn * Hn];
__device__ __nv_bfloat16 g_shi[(size_t)TBn * Hn];   // hseq hi (GEMM A input)
__device__ __nv_bfloat16 g_slo[(size_t)TBn * Hn];   // hseq lo
__device__ __nv_bfloat16 g_ahi[(size_t)TBn * Hn];   // x split
__device__ __nv_bfloat16 g_alo[(size_t)TBn * Hn];
__device__ __nv_bfloat16 g_whi[(size_t)Gn * Hn];
__device__ __nv_bfloat16 g_wlo[(size_t)Gn * Hn];

__device__ __forceinline__ float sigf(float x) { return 1.0f / (1.0f + expf(-x)); }

__device__ __forceinline__ uint32_t smem_u32(const void* p) {
    uint32_t a;
    asm("{ .reg .u64 t; cvta.to.shared.u64 t, %1; cvt.u32.u64 %0, t; }"
        : "=r"(a) : "l"(p));
    return a;
}
__device__ __forceinline__ void cpasync16(uint32_t dst, const void* src) {
    asm volatile("cp.async.cg.shared.global [%0], [%1], 16;"
                 :: "r"(dst), "l"(src) : "memory");
}
__device__ __forceinline__ void cp_commit() {
    asm volatile("cp.async.commit_group;" ::: "memory");
}
__device__ __forceinline__ void ldsm4(uint32_t& r0, uint32_t& r1, uint32_t& r2,
                                      uint32_t& r3, uint32_t addr) {
    asm volatile("ldmatrix.sync.aligned.m8n8.x4.shared.b16 {%0,%1,%2,%3}, [%4];"
                 : "=r"(r0), "=r"(r1), "=r"(r2), "=r"(r3) : "r"(addr));
}
__device__ __forceinline__ void mma16816(float* c, uint32_t a0, uint32_t a1,
                                         uint32_t a2, uint32_t a3,
                                         uint32_t b0, uint32_t b1) {
    asm volatile(
        "mma.sync.aligned.m16n8k16.row.col.f32.bf16.bf16.f32 "
        "{%0,%1,%2,%3}, {%4,%5,%6,%7}, {%8,%9}, {%0,%1,%2,%3};"
        : "+f"(c[0]), "+f"(c[1]), "+f"(c[2]), "+f"(c[3])
        : "r"(a0), "r"(a1), "r"(a2), "r"(a3), "r"(b0), "r"(b1));
}

// ------- per-group split barrier: arrive now, wait one group-phase later ---
__device__ __forceinline__ void arrive_h(int g, unsigned ph) {
    __syncthreads();
    if (threadIdx.x == 0) {
        __threadfence();
        asm volatile("st.release.gpu.global.u32 [%0], %1;"
                     :: "l"(&g_arr[g][blockIdx.x]), "r"(ph) : "memory");
    }
}
__device__ __forceinline__ void wait_h(int g, unsigned ph) {
    if (blockIdx.x == 0) {
        if (threadIdx.x < NCTA) {
            unsigned v;
            do {
                asm volatile("ld.acquire.gpu.global.u32 %0, [%1];"
                             : "=r"(v) : "l"(&g_arr[g][threadIdx.x]));
            } while ((int)(v - ph) < 0);
        }
        __syncthreads();
        if (threadIdx.x == 0) {
            __threadfence();
            asm volatile("st.release.gpu.global.u32 [%0], %1;"
                         :: "l"(&g_gen[g]), "r"(ph) : "memory");
        }
    } else if (threadIdx.x == 0) {
        unsigned v;
        do {
            asm volatile("ld.acquire.gpu.global.u32 %0, [%1];"
                         : "=r"(v) : "l"(&g_gen[g]));
        } while ((int)(v - ph) < 0);
    }
    __syncthreads();
}

// ---------------------------------------------------------------------------
// Persistent HMMA LSTM layer with 2 batch groups software-pipelined.
// CTA owns 32 W_hh rows (4 gates x 8 j-cols), bf16 hi/lo in SMEM.
// Per step: phase(group0) then phase(group1); each group's barrier+h round
// trip is hidden behind the other group's compute.
// Warp layout per phase: kq(4 k-quarters of 256) x mi(2 of 16 batches) x nz(2).
// ---------------------------------------------------------------------------
__global__ void __launch_bounds__(NTHR, 1)
lstm_recur(const float* __restrict__ Whh, const float* __restrict__ pre,
           __nv_bfloat16* __restrict__ shi, __nv_bfloat16* __restrict__ slo)
{
    extern __shared__ char smc[];
    const uint32_t sb = smem_u32(smc);
    const int tid = threadIdx.x;
    const int lane = tid & 31, wid = tid >> 5;
    const int kq = wid >> 2, mi = (wid >> 1) & 1, nz = wid & 1;
    const int cta = blockIdx.x;
    const int j0  = cta * 8;

    unsigned phase0;
    asm volatile("ld.acquire.gpu.global.u32 %0, [%1];"
                 : "=r"(phase0) : "l"(&g_arr[0][cta]));

    // ---- Load & split W slice into SMEM (vectorized, once per layer) ----
#pragma unroll
    for (int l = 0; l < 16; l++) {
        int f = tid + l * NTHR;          // float4 index, 0..8191
        int r = f >> 8, k4 = (f & 255) * 4;
        float4 v = __ldg((const float4*)(Whh
                     + (size_t)((r >> 3) * Hn + j0 + (r & 7)) * Hn + k4));
        __nv_bfloat16 h0 = __float2bfloat16(v.x), h1 = __float2bfloat16(v.y);
        __nv_bfloat16 h2 = __float2bfloat16(v.z), h3 = __float2bfloat16(v.w);
        __nv_bfloat16 l0 = __float2bfloat16(v.x - __bfloat162float(h0));
        __nv_bfloat16 l1 = __float2bfloat16(v.y - __bfloat162float(h1));
        __nv_bfloat16 l2 = __float2bfloat16(v.z - __bfloat162float(h2));
        __nv_bfloat16 l3 = __float2bfloat16(v.w - __bfloat162float(h3));
        char* dh = smc + r * RWS + k4 * 2;
        char* dl = smc + W_LO_OFF + r * RWS + k4 * 2;
        *(__nv_bfloat162*)(dh)     = __nv_bfloat162(h0, h1);
        *(__nv_bfloat162*)(dh + 4) = __nv_bfloat162(h2, h3);
        *(__nv_bfloat162*)(dl)     = __nv_bfloat162(l0, l1);
        *(__nv_bfloat162*)(dl + 4) = __nv_bfloat162(l2, l3);
    }
    __syncthreads();

    // ldmatrix address templates
    const uint32_t a_lane = (uint32_t)((mi * 16 + (lane & 15)) * A_CSTR
                                       + (lane >> 4) * 16);
    const uint32_t b_lane = (uint32_t)((nz * 16 + (lane & 7) + ((lane >> 4) << 3)) * RWS
                                       + ((lane >> 3) & 1) * 16);

    const int pbl = tid >> 3;             // pointwise local batch (0..63; use <32)
    const int jx  = tid & 7;              // pointwise j within slice

    // A stage loader: one 64-k slice per quarter, hi+lo; 4 x 16B per thread
    auto load_stage = [&](int st, int g, int ck) {
#pragma unroll
        for (int l = 0; l < 4; l++) {
            int idx = tid + l * NTHR;        // 0..2047
            int sel = idx >> 10;             // 0 = hi, 1 = lo
            int r = idx & 1023;
            int q = r >> 8, row = (r >> 3) & 31, c16 = r & 7;
            uint32_t dst = sb + A_OFF + st * A_STAGE + sel * A_SELB
                         + q * A_QB + row * A_CSTR + c16 * 16;
            const __nv_bfloat16* src = (sel ? g_hlo : g_hhi)
                + (size_t)(g * 32 + row) * Hn + q * 256 + ck * 64 + c16 * 8;
            cpasync16(dst, src);
        }
        cp_commit();
    };

    for (int t = 0; t < Tn; t++) {
#pragma unroll
        for (int g = 0; g < 2; g++) {
            const int gb = g * 32 + pbl;     // global batch for pointwise (pbl<32)
            // early-issue pre loads (independent of barrier)
            float qi = 0, qf = 0, qg = 0, qo = 0;
            if (pbl < 32) {
                size_t pbase = (size_t)t * ((size_t)Bn * Gn) + (size_t)gb * Gn + j0 + jx;
                qi = __ldg(pre + pbase);
                qf = __ldg(pre + pbase + Hn);
                qg = __ldg(pre + pbase + 2 * Hn);
                qo = __ldg(pre + pbase + 3 * Hn);
            }

            wait_h(g, phase0 + t);           // h_g(t) ready (t=0 passes)
            load_stage(0, g, 0);

            float acc[2][4];
#pragma unroll
            for (int n = 0; n < 2; n++)
#pragma unroll
                for (int i = 0; i < 4; i++) acc[n][i] = 0.0f;

            for (int ck = 0; ck < 4; ck++) {
                const int st = ck & 1;
                asm volatile("cp.async.wait_group 0;" ::: "memory");
                __syncthreads();
                if (ck + 1 < 4) load_stage(st ^ 1, g, ck + 1);

                const uint32_t abase = sb + A_OFF + st * A_STAGE
                                     + kq * A_QB + a_lane;
#pragma unroll
                for (int kb = 0; kb < 4; kb++) {
                    uint32_t ah0, ah1, ah2, ah3, al0, al1, al2, al3;
                    ldsm4(ah0, ah1, ah2, ah3, abase + kb * 32);
                    ldsm4(al0, al1, al2, al3, abase + A_SELB + kb * 32);
                    uint32_t bkoff = (uint32_t)(kq * 512 + ck * 128 + kb * 32);
                    uint32_t bh0, bh1, bh2, bh3, bl0, bl1, bl2, bl3;
                    ldsm4(bh0, bh1, bh2, bh3, sb + b_lane + bkoff);
                    ldsm4(bl0, bl1, bl2, bl3, sb + W_LO_OFF + b_lane + bkoff);
                    mma16816(acc[0], ah0, ah1, ah2, ah3, bh0, bh1);
                    mma16816(acc[0], ah0, ah1, ah2, ah3, bl0, bl1);
                    mma16816(acc[0], al0, al1, al2, al3, bh0, bh1);
                    mma16816(acc[1], ah0, ah1, ah2, ah3, bh2, bh3);
                    mma16816(acc[1], ah0, ah1, ah2, ah3, bl2, bl3);
                    mma16816(acc[1], al0, al1, al2, al3, bh2, bh3);
                }
            }

            // Epilogue: fragments -> this quarter's gate smem [32 b][32 n]
            float* gsm = (float*)(smc + GSM_OFF + kq * GSM_QB);
            {
                int rl = mi * 16 + (lane >> 2);
#pragma unroll
                for (int nt = 0; nt < 2; nt++) {
                    int c0 = nz * 16 + nt * 8 + (lane & 3) * 2;
                    *(float2*)(gsm + rl * GSTR + c0) =
                        make_float2(acc[nt][0], acc[nt][1]);
                    *(float2*)(gsm + (rl + 8) * GSTR + c0) =
                        make_float2(acc[nt][2], acc[nt][3]);
                }
            }
            __syncthreads();

            // Pointwise: threads with pbl<32, 1 cell each, summing 4 quarters
            if (pbl < 32) {
                float ri = 0, rf = 0, rg = 0, ro = 0;
#pragma unroll
                for (int q = 0; q < 4; q++) {
                    const float* gq = (const float*)(smc + GSM_OFF + q * GSM_QB)
                                    + pbl * GSTR;
                    ri += gq[jx];      rf += gq[8 + jx];
                    rg += gq[16 + jx]; ro += gq[24 + jx];
                }
                float* cp0 = g_c + (size_t)gb * Hn + j0 + jx;
                float cc = (t == 0) ? 0.0f : cp0[0];

                float ig = sigf(ri + qi);
                float fg = sigf(rf + qf);
                float gg = tanhf(rg + qg);
                float og = sigf(ro + qo);
                cc = fg * cc + ig * gg;
                cp0[0] = cc;
                float hh = og * tanhf(cc);

                __nv_bfloat16 hhB = __float2bfloat16(hh);
                __nv_bfloat16 hlB = __float2bfloat16(hh - __bfloat162float(hhB));
                size_t hidx = (size_t)gb * Hn + j0 + jx;
                g_hhi[hidx] = hhB;
                g_hlo[hidx] = hlB;
                size_t sidx = (size_t)t * Bn * Hn + hidx;
                shi[sidx] = hhB;
                slo[sidx] = hlB;
            }

            arrive_h(g, phase0 + t + 1);     // starts with __syncthreads
        }
    }
}

// ---------------------------------------------------------------------------
// fp32 -> bf16 hi/lo split conversion (elementwise)
// ---------------------------------------------------------------------------
__global__ void cvt_split(const float* __restrict__ in,
                          __nv_bfloat16* __restrict__ hi,
                          __nv_bfloat16* __restrict__ lo, int n4)
{
    int i = blockIdx.x * blockDim.x + threadIdx.x;
    if (i >= n4) return;
    float4 v = __ldg((const float4*)in + i);
    __nv_bfloat16 h0 = __float2bfloat16(v.x);
    __nv_bfloat16 h1 = __float2bfloat16(v.y);
    __nv_bfloat16 h2 = __float2bfloat16(v.z);
    __nv_bfloat16 h3 = __float2bfloat16(v.w);
    __nv_bfloat16 l0 = __float2bfloat16(v.x - __bfloat162float(h0));
    __nv_bfloat16 l1 = __float2bfloat16(v.y - __bfloat162float(h1));
    __nv_bfloat16 l2 = __float2bfloat16(v.z - __bfloat162float(h2));
    __nv_bfloat16 l3 = __float2bfloat16(v.w - __bfloat162float(h3));
    *((__nv_bfloat162*)hi + 2*i)     = __nv_bfloat162(h0, h1);
    *((__nv_bfloat162*)hi + 2*i + 1) = __nv_bfloat162(h2, h3);
    *((__nv_bfloat162*)lo + 2*i)     = __nv_bfloat162(l0, l1);
    *((__nv_bfloat162*)lo + 2*i + 1) = __nv_bfloat162(l2, l3);
}

// ---------------------------------------------------------------------------
// HMMA bf16-split GEMM (R7-proven): C = (Ahi+Alo) @ (Whi+Wlo)^T + bias
// ---------------------------------------------------------------------------
__global__ void __launch_bounds__(256, 1)
gemm_tc(const __nv_bfloat16* __restrict__ Ahi, const __nv_bfloat16* __restrict__ Alo,
        const __nv_bfloat16* __restrict__ Whi, const __nv_bfloat16* __restrict__ Wlo,
        const float* __restrict__ b0, const float* __restrict__ b1,
        float* __restrict__ C, int K, int N)
{
    extern __shared__ char smc[];
    const uint32_t sb = smem_u32(smc);
    const int tid = threadIdx.x, lane = tid & 31, wid = tid >> 5;
    const int m0 = blockIdx.y * BM, n0 = blockIdx.x * BN;
    const int wm = (wid & 1) * 64, wn = (wid >> 1) * 32;

    float acc[4][4][4];
#pragma unroll
    for (int i = 0; i < 4; i++)
#pragma unroll
        for (int j = 0; j < 4; j++)
#pragma unroll
            for (int l = 0; l < 4; l++) acc[i][j][l] = 0.0f;

    const int r0l = tid >> 2, ch0 = (tid & 3);
    const int r1l = (tid + 256) >> 2, ch1 = ((tid + 256) & 3);
    const int NS = K / BK;

    auto load_stage = [&](int st, int ck) {
        uint32_t sbase = sb + st * STGB;
        const __nv_bfloat16* ap;
        ap = Ahi + (size_t)(m0 + r0l) * K + ck * BK + ch0 * 8;
        cpasync16(sbase + 0*MATB + r0l * ROWB + ch0 * 16, ap);
        ap = Ahi + (size_t)(m0 + r1l) * K + ck * BK + ch1 * 8;
        cpasync16(sbase + 0*MATB + r1l * ROWB + ch1 * 16, ap);
        ap = Alo + (size_t)(m0 + r0l) * K + ck * BK + ch0 * 8;
        cpasync16(sbase + 1*MATB + r0l * ROWB + ch0 * 16, ap);
        ap = Alo + (size_t)(m0 + r1l) * K + ck * BK + ch1 * 8;
        cpasync16(sbase + 1*MATB + r1l * ROWB + ch1 * 16, ap);
        ap = Whi + (size_t)(n0 + r0l) * K + ck * BK + ch0 * 8;
        cpasync16(sbase + 2*MATB + r0l * ROWB + ch0 * 16, ap);
        ap = Whi + (size_t)(n0 + r1l) * K + ck * BK + ch1 * 8;
        cpasync16(sbase + 2*MATB + r1l * ROWB + ch1 * 16, ap);
        ap = Wlo + (size_t)(n0 + r0l) * K + ck * BK + ch0 * 8;
        cpasync16(sbase + 3*MATB + r0l * ROWB + ch0 * 16, ap);
        ap = Wlo + (size_t)(n0 + r1l) * K + ck * BK + ch1 * 8;
        cpasync16(sbase + 3*MATB + r1l * ROWB + ch1 * 16, ap);
        cp_commit();
    };

    load_stage(0, 0);

    const uint32_t aoff = (uint32_t)((wm + (lane & 15)) * ROWB + (lane >> 4) * 16);
    const uint32_t boff = (uint32_t)((wn + (lane & 7) + ((lane >> 4) << 3)) * ROWB
                                     + ((lane >> 3) & 1) * 16);

    for (int ck = 0; ck < NS; ck++) {
        const int st = ck & 1;
        if (ck + 1 < NS) {
            load_stage(st ^ 1, ck + 1);
            asm volatile("cp.async.wait_group 1;" ::: "memory");
        } else {
            asm volatile("cp.async.wait_group 0;" ::: "memory");
        }
        __syncthreads();

        const uint32_t sbase = sb + st * STGB;
#pragma unroll
        for (int kk = 0; kk < 2; kk++) {
            const uint32_t ko = kk * 32;
            uint32_t bh[2][4], bl[2][4];
#pragma unroll
            for (int nb = 0; nb < 2; nb++) {
                uint32_t ba = sbase + boff + nb * (16 * ROWB) + ko;
                ldsm4(bh[nb][0], bh[nb][1], bh[nb][2], bh[nb][3], ba + 2*MATB);
                ldsm4(bl[nb][0], bl[nb][1], bl[nb][2], bl[nb][3], ba + 3*MATB);
            }
            uint32_t ah[4][4], al[4][4];
#pragma unroll
            for (int mi = 0; mi < 4; mi++) {
                uint32_t aa = sbase + aoff + mi * (16 * ROWB) + ko;
                ldsm4(ah[mi][0], ah[mi][1], ah[mi][2], ah[mi][3], aa);
                ldsm4(al[mi][0], al[mi][1], al[mi][2], al[mi][3], aa + MATB);
            }
#pragma unroll
            for (int mi = 0; mi < 4; mi++) {
#pragma unroll
                for (int ni = 0; ni < 4; ni++) {
                    const int nb = ni >> 1, pr = (ni & 1) * 2;
                    float* c = acc[mi][ni];
                    mma16816(c, ah[mi][0], ah[mi][1], ah[mi][2], ah[mi][3],
                             bh[nb][pr], bh[nb][pr + 1]);
                    mma16816(c, ah[mi][0], ah[mi][1], ah[mi][2], ah[mi][3],
                             bl[nb][pr], bl[nb][pr + 1]);
                    mma16816(c, al[mi][0], al[mi][1], al[mi][2], al[mi][3],
                             bh[nb][pr], bh[nb][pr + 1]);
                }
            }
        }
        __syncthreads();
    }

#pragma unroll
    for (int ni = 0; ni < 4; ni++) {
        int cc = n0 + wn + ni * 8 + (lane & 3) * 2;
        float bb0 = __ldg(b0 + cc) + (b1 ? __ldg(b1 + cc) : 0.0f);
        float bb1 = __ldg(b0 + cc + 1) + (b1 ? __ldg(b1 + cc + 1) : 0.0f);
#pragma unroll
        for (int mi = 0; mi < 4; mi++) {
            int rr = m0 + wm + mi * 16 + (lane >> 2);
            float* c = acc[mi][ni];
            *(float2*)(C + (size_t)rr * N + cc) =
                make_float2(c[0] + bb0, c[1] + bb1);
            *(float2*)(C + (size_t)(rr + 8) * N + cc) =
                make_float2(c[2] + bb0, c[3] + bb1);
        }
    }
}

// ---------------------------------------------------------------------------
extern "C" void kernel_launch(void* const* d_in, const int* in_sizes, int n_in,
                              void* d_out, int out_size)
{
    const float* x    = (const float*)d_in[0];
    const float* Wih0 = (const float*)d_in[1];
    const float* Whh0 = (const float*)d_in[2];
    const float* bih0 = (const float*)d_in[3];
    const float* bhh0 = (const float*)d_in[4];
    const float* Wih1 = (const float*)d_in[5];
    const float* Whh1 = (const float*)d_in[6];
    const float* bih1 = (const float*)d_in[7];
    const float* bhh1 = (const float*)d_in[8];
    const float* Wout = (const float*)d_in[9];
    const float* bout = (const float*)d_in[10];
    float* out = (float*)d_out;

    float* pre;
    __nv_bfloat16 *ahi, *alo, *whi, *wlo, *shi, *slo, *hhi, *hlo;
    cudaGetSymbolAddress((void**)&pre, g_pre);
    cudaGetSymbolAddress((void**)&ahi, g_ahi);
    cudaGetSymbolAddress((void**)&alo, g_alo);
    cudaGetSymbolAddress((void**)&whi, g_whi);
    cudaGetSymbolAddress((void**)&wlo, g_wlo);
    cudaGetSymbolAddress((void**)&shi, g_shi);
    cudaGetSymbolAddress((void**)&slo, g_slo);
    cudaGetSymbolAddress((void**)&hhi, g_hhi);
    cudaGetSymbolAddress((void**)&hlo, g_hlo);

    cudaFuncSetAttribute(lstm_recur, cudaFuncAttributeMaxDynamicSharedMemorySize,
                         SMEM_RECUR);
    cudaFuncSetAttribute(gemm_tc, cudaFuncAttributeMaxDynamicSharedMemorySize,
                         SMEM_GEMM);

    // ---- Layer 0 ----
    cvt_split<<<(TBn*In/4 + 255)/256, 256>>>(x, ahi, alo, TBn*In/4);
    cvt_split<<<(Gn*In/4 + 255)/256, 256>>>(Wih0, whi, wlo, Gn*In/4);
    gemm_tc<<<dim3(Gn/BN, TBn/BM), 256, SMEM_GEMM>>>(
        ahi, alo, whi, wlo, bih0, bhh0, pre, In, Gn);
    cudaMemsetAsync(hhi, 0, sizeof(__nv_bfloat16)*Bn*Hn);
    cudaMemsetAsync(hlo, 0, sizeof(__nv_bfloat16)*Bn*Hn);
    lstm_recur<<<NCTA, NTHR, SMEM_RECUR>>>(Whh0, pre, shi, slo);

    // ---- Layer 1 (A = hseq hi/lo directly) ----
    cvt_split<<<(Gn*Hn/4 + 255)/256, 256>>>(Wih1, whi, wlo, Gn*Hn/4);
    gemm_tc<<<dim3(Gn/BN, TBn/BM), 256, SMEM_GEMM>>>(
        shi, slo, whi, wlo, bih1, bhh1, pre, Hn, Gn);
    cudaMemsetAsync(hhi, 0, sizeof(__nv_bfloat16)*Bn*Hn);
    cudaMemsetAsync(hlo, 0, sizeof(__nv_bfloat16)*Bn*Hn);
    lstm_recur<<<NCTA, NTHR, SMEM_RECUR>>>(Whh1, pre, shi, slo);

    // ---- Output projection (A = hseq hi/lo) ----
    cvt_split<<<(On*Hn/4 + 255)/256, 256>>>(Wout, whi, wlo, On*Hn/4);
    gemm_tc<<<dim3(On/BN, TBn/BM), 256, SMEM_GEMM>>>(
        shi, slo, whi, wlo, bout, nullptr, out, Hn, On);
}

// round 17
// speedup vs baseline: 1.2009x; 1.2009x over previous
#include <cuda_runtime.h>
#include <cuda_bf16.h>
#include <math.h>
#include <stdint.h>

// Problem dims
#define Tn 512
#define Bn 64
#define In 512
#define Hn 1024
#define On 512
#define Gn 4096
#define TBn (Tn*Bn)           // 32768

#define NCTA 128
#define NTHR 512              // 16 warps, k-split 2

// ---- recurrence smem layout (bytes) ----
#define RWS 2064                       // W row stride (1024 bf16 + 16B pad)
#define W_LO_OFF (32*RWS)              // 66048
#define A_OFF    (2*32*RWS)            // 132096
#define A_CSTR   144                   // 64 k-bf16 (128B) + 16B pad
#define A_HMAT   (64*A_CSTR)           // 9216 (one matrix: hi or lo)
#define A_STAGE  (2*A_HMAT)            // 18432 (hi+lo)
#define A_KZ     (2*A_STAGE)           // 36864 per k-half (2 stages)
#define GSM_OFF  (A_OFF + 2*A_KZ)      // 205824
#define GSTR 34                        // even: float2 stays 8B-aligned
#define GSM_HALF (64*GSTR*4)           // 8704
#define SMEM_RECUR (GSM_OFF + 2*GSM_HALF) // 223232

// ---- HMMA GEMM tile config: BK=64 ----
#define BM 128
#define BN 128
#define BK 64
#define ROWB 144                   // 64 bf16 (128B) + 16B pad; 36%32=4 -> conflict-free
#define MATB (128*ROWB)            // 18432
#define STGB (4*MATB)              // 73728
#define SMEM_GEMM (2*STGB)         // 147456

// Scratch (device globals)
__device__ float g_pre[(size_t)TBn * Gn];
__device__ unsigned g_arrive[NCTA] = {};
__device__ unsigned g_bar_gen = 0;
__device__ __nv_bfloat16 g_hhi[Bn * Hn];
__device__ __nv_bfloat16 g_hlo[Bn * Hn];
__device__ __nv_bfloat16 g_shi[(size_t)TBn * Hn];   // hseq hi (GEMM A input)
__device__ __nv_bfloat16 g_slo[(size_t)TBn * Hn];   // hseq lo
__device__ __nv_bfloat16 g_ahi[(size_t)TBn * Hn];   // x split
__device__ __nv_bfloat16 g_alo[(size_t)TBn * Hn];
__device__ __nv_bfloat16 g_whi[(size_t)Gn * Hn];
__device__ __nv_bfloat16 g_wlo[(size_t)Gn * Hn];

__device__ __forceinline__ float sigf(float x) { return 1.0f / (1.0f + expf(-x)); }

__device__ __forceinline__ uint32_t smem_u32(const void* p) {
    uint32_t a;
    asm("{ .reg .u64 t; cvta.to.shared.u64 t, %1; cvt.u32.u64 %0, t; }"
        : "=r"(a) : "l"(p));
    return a;
}
__device__ __forceinline__ void cpasync16(uint32_t dst, const void* src) {
    asm volatile("cp.async.cg.shared.global [%0], [%1], 16;"
                 :: "r"(dst), "l"(src) : "memory");
}
__device__ __forceinline__ void cp_commit() {
    asm volatile("cp.async.commit_group;" ::: "memory");
}
__device__ __forceinline__ void ldsm4(uint32_t& r0, uint32_t& r1, uint32_t& r2,
                                      uint32_t& r3, uint32_t addr) {
    asm volatile("ldmatrix.sync.aligned.m8n8.x4.shared.b16 {%0,%1,%2,%3}, [%4];"
                 : "=r"(r0), "=r"(r1), "=r"(r2), "=r"(r3) : "r"(addr));
}
__device__ __forceinline__ void mma16816(float* c, uint32_t a0, uint32_t a1,
                                         uint32_t a2, uint32_t a3,
                                         uint32_t b0, uint32_t b1) {
    asm volatile(
        "mma.sync.aligned.m16n8k16.row.col.f32.bf16.bf16.f32 "
        "{%0,%1,%2,%3}, {%4,%5,%6,%7}, {%8,%9}, {%0,%1,%2,%3};"
        : "+f"(c[0]), "+f"(c[1]), "+f"(c[2]), "+f"(c[3])
        : "r"(a0), "r"(a1), "r"(a2), "r"(a3), "r"(b0), "r"(b1));
}

// ------- two-round grid barrier (R9-proven; waiters poll ONE cacheline) ----
__device__ __forceinline__ void grid_sync(unsigned phase) {
    __syncthreads();
    if (threadIdx.x == 0) {
        __threadfence();
        asm volatile("st.release.gpu.global.u32 [%0], %1;"
                     :: "l"(&g_arrive[blockIdx.x]), "r"(phase) : "memory");
    }
    if (blockIdx.x == 0) {
        if (threadIdx.x < NCTA) {
            unsigned v;
            do {
                asm volatile("ld.acquire.gpu.global.u32 %0, [%1];"
                             : "=r"(v) : "l"(&g_arrive[threadIdx.x]));
            } while (v != phase);
        }
        __syncthreads();
        if (threadIdx.x == 0) {
            __threadfence();
            asm volatile("st.release.gpu.global.u32 [%0], %1;"
                         :: "l"(&g_bar_gen), "r"(phase) : "memory");
        }
    } else if (threadIdx.x == 0) {
        unsigned v;
        do {
            asm volatile("ld.acquire.gpu.global.u32 %0, [%1];"
                         : "=r"(v) : "l"(&g_bar_gen));
        } while (v != phase);
    }
    __syncthreads();
}

// ---------------------------------------------------------------------------
// Persistent HMMA LSTM layer, 512 threads, k-split 2 (R14-proven).
// Cell state lives in a REGISTER (fixed thread<->cell map) — no global c.
// ---------------------------------------------------------------------------
__global__ void __launch_bounds__(NTHR, 1)
lstm_recur(const float* __restrict__ Whh, const float* __restrict__ pre,
           __nv_bfloat16* __restrict__ shi, __nv_bfloat16* __restrict__ slo)
{
    extern __shared__ char smc[];
    const uint32_t sb = smem_u32(smc);
    const int tid = threadIdx.x;
    const int lane = tid & 31;
    const int kz  = tid >> 8;            // k-split half
    const int hid = tid & 255;
    const int wid8 = hid >> 5;           // warp within half
    const int mi = wid8 & 3, nz = wid8 >> 2;
    const int cta = blockIdx.x;
    const int j0  = cta * 8;

    unsigned phase0;
    asm volatile("ld.acquire.gpu.global.u32 %0, [%1];" : "=r"(phase0) : "l"(&g_bar_gen));

    // ---- Load & split W slice into SMEM (vectorized, once per layer) ----
#pragma unroll
    for (int l = 0; l < 16; l++) {
        int f = tid + l * NTHR;          // float4 index, 0..8191
        int r = f >> 8, k4 = (f & 255) * 4;
        float4 v = __ldg((const float4*)(Whh
                     + (size_t)((r >> 3) * Hn + j0 + (r & 7)) * Hn + k4));
        __nv_bfloat16 h0 = __float2bfloat16(v.x), h1 = __float2bfloat16(v.y);
        __nv_bfloat16 h2 = __float2bfloat16(v.z), h3 = __float2bfloat16(v.w);
        __nv_bfloat16 l0 = __float2bfloat16(v.x - __bfloat162float(h0));
        __nv_bfloat16 l1 = __float2bfloat16(v.y - __bfloat162float(h1));
        __nv_bfloat16 l2 = __float2bfloat16(v.z - __bfloat162float(h2));
        __nv_bfloat16 l3 = __float2bfloat16(v.w - __bfloat162float(h3));
        char* dh = smc + r * RWS + k4 * 2;
        char* dl = smc + W_LO_OFF + r * RWS + k4 * 2;
        *(__nv_bfloat162*)(dh)     = __nv_bfloat162(h0, h1);
        *(__nv_bfloat162*)(dh + 4) = __nv_bfloat162(h2, h3);
        *(__nv_bfloat162*)(dl)     = __nv_bfloat162(l0, l1);
        *(__nv_bfloat162*)(dl + 4) = __nv_bfloat162(l2, l3);
    }
    __syncthreads();

    // ldmatrix address templates
    const uint32_t a_lane = (uint32_t)((mi * 16 + (lane & 15)) * A_CSTR
                                       + (lane >> 4) * 16);
    const uint32_t b_lane = (uint32_t)((nz * 16 + (lane & 7) + ((lane >> 4) << 3)) * RWS
                                       + ((lane >> 3) & 1) * 16);

    const int pb = tid >> 3;              // pointwise batch (0..63)
    const int jx = tid & 7;               // pointwise j within slice
    float cst = 0.0f;                     // cell state in REGISTER

    // A stage loader: this half's k range, chunks of k=64; hi+lo
    auto load_stage = [&](int st, int ck) {
#pragma unroll
        for (int l = 0; l < 4; l++) {
            int idx = hid + l * 256;         // 0..1023
            int sel = idx >> 9;              // 0 = hi, 1 = lo
            int i = idx & 511;
            int row = i >> 3, c16 = i & 7;
            uint32_t dst = sb + A_OFF + kz * A_KZ + st * A_STAGE + sel * A_HMAT
                         + row * A_CSTR + c16 * 16;
            const __nv_bfloat16* src = (sel ? g_hlo : g_hhi)
                                       + row * Hn + kz * 512 + ck * 64 + c16 * 8;
            cpasync16(dst, src);
        }
        cp_commit();
    };

    for (int t = 0; t < Tn; t++) {
        // early-issue pre loads
        size_t pbase = (size_t)t * ((size_t)Bn * Gn) + (size_t)pb * Gn + j0 + jx;
        float qi = __ldg(pre + pbase);
        float qf = __ldg(pre + pbase + Hn);
        float qg = __ldg(pre + pbase + 2 * Hn);
        float qo = __ldg(pre + pbase + 3 * Hn);

        float acc[2][4];
#pragma unroll
        for (int n = 0; n < 2; n++)
#pragma unroll
            for (int i = 0; i < 4; i++) acc[n][i] = 0.0f;

        load_stage(0, 0);

        for (int ck = 0; ck < 8; ck++) {
            const int st = ck & 1;
            asm volatile("cp.async.wait_group 0;" ::: "memory");
            __syncthreads();
            if (ck + 1 < 8) load_stage(st ^ 1, ck + 1);

            const uint32_t ahbase = sb + A_OFF + kz * A_KZ + st * A_STAGE + a_lane;
#pragma unroll
            for (int kb = 0; kb < 4; kb++) {
                uint32_t ah0, ah1, ah2, ah3, al0, al1, al2, al3;
                ldsm4(ah0, ah1, ah2, ah3, ahbase + kb * 32);
                ldsm4(al0, al1, al2, al3, ahbase + A_HMAT + kb * 32);
                uint32_t bkoff = (uint32_t)(kz * 1024 + ck * 128 + kb * 32);
                uint32_t bh0, bh1, bh2, bh3, bl0, bl1, bl2, bl3;
                ldsm4(bh0, bh1, bh2, bh3, sb + b_lane + bkoff);
                ldsm4(bl0, bl1, bl2, bl3, sb + W_LO_OFF + b_lane + bkoff);
                mma16816(acc[0], ah0, ah1, ah2, ah3, bh0, bh1);
                mma16816(acc[0], ah0, ah1, ah2, ah3, bl0, bl1);
                mma16816(acc[0], al0, al1, al2, al3, bh0, bh1);
                mma16816(acc[1], ah0, ah1, ah2, ah3, bh2, bh3);
                mma16816(acc[1], ah0, ah1, ah2, ah3, bl2, bl3);
                mma16816(acc[1], al0, al1, al2, al3, bh2, bh3);
            }
        }

        // Epilogue: fragments -> this half's gate smem [b 64][n 32]
        float* gsm = (float*)(smc + GSM_OFF + kz * GSM_HALF);
        {
            int rl = mi * 16 + (lane >> 2);
#pragma unroll
            for (int nt = 0; nt < 2; nt++) {
                int c0 = nz * 16 + nt * 8 + (lane & 3) * 2;
                *(float2*)(gsm + rl * GSTR + c0)       = make_float2(acc[nt][0], acc[nt][1]);
                *(float2*)(gsm + (rl + 8) * GSTR + c0) = make_float2(acc[nt][2], acc[nt][3]);
            }
        }
        __syncthreads();

        // Pointwise: 1 cell per thread, combining both k-halves; c in register
        {
            const float* g0 = (const float*)(smc + GSM_OFF) + pb * GSTR;
            const float* g1 = (const float*)(smc + GSM_OFF + GSM_HALF) + pb * GSTR;
            float ri = g0[jx]      + g1[jx];
            float rf = g0[8 + jx]  + g1[8 + jx];
            float rg = g0[16 + jx] + g1[16 + jx];
            float ro = g0[24 + jx] + g1[24 + jx];

            float ig = sigf(ri + qi);
            float fg = sigf(rf + qf);
            float gg = tanhf(rg + qg);
            float og = sigf(ro + qo);
            cst = fg * cst + ig * gg;
            float hh = og * tanhf(cst);

            __nv_bfloat16 hhB = __float2bfloat16(hh);
            __nv_bfloat16 hlB = __float2bfloat16(hh - __bfloat162float(hhB));

            int hidx = pb * Hn + j0 + jx;
            g_hhi[hidx] = hhB;
            g_hlo[hidx] = hlB;
            size_t sidx = (size_t)t * Bn * Hn + hidx;
            shi[sidx] = hhB;
            slo[sidx] = hlB;
        }

        grid_sync(phase0 + t + 1);
    }
}

// ---------------------------------------------------------------------------
// fp32 -> bf16 hi/lo split conversion (elementwise)
// ---------------------------------------------------------------------------
__global__ void cvt_split(const float* __restrict__ in,
                          __nv_bfloat16* __restrict__ hi,
                          __nv_bfloat16* __restrict__ lo, int n4)
{
    int i = blockIdx.x * blockDim.x + threadIdx.x;
    if (i >= n4) return;
    float4 v = __ldg((const float4*)in + i);
    __nv_bfloat16 h0 = __float2bfloat16(v.x);
    __nv_bfloat16 h1 = __float2bfloat16(v.y);
    __nv_bfloat16 h2 = __float2bfloat16(v.z);
    __nv_bfloat16 h3 = __float2bfloat16(v.w);
    __nv_bfloat16 l0 = __float2bfloat16(v.x - __bfloat162float(h0));
    __nv_bfloat16 l1 = __float2bfloat16(v.y - __bfloat162float(h1));
    __nv_bfloat16 l2 = __float2bfloat16(v.z - __bfloat162float(h2));
    __nv_bfloat16 l3 = __float2bfloat16(v.w - __bfloat162float(h3));
    *((__nv_bfloat162*)hi + 2*i)     = __nv_bfloat162(h0, h1);
    *((__nv_bfloat162*)hi + 2*i + 1) = __nv_bfloat162(h2, h3);
    *((__nv_bfloat162*)lo + 2*i)     = __nv_bfloat162(l0, l1);
    *((__nv_bfloat162*)lo + 2*i + 1) = __nv_bfloat162(l2, l3);
}

// ---------------------------------------------------------------------------
// HMMA bf16-split GEMM, BK=64: C = (Ahi+Alo) @ (Whi+Wlo)^T + bias
// ---------------------------------------------------------------------------
__global__ void __launch_bounds__(256, 1)
gemm_tc(const __nv_bfloat16* __restrict__ Ahi, const __nv_bfloat16* __restrict__ Alo,
        const __nv_bfloat16* __restrict__ Whi, const __nv_bfloat16* __restrict__ Wlo,
        const float* __restrict__ b0, const float* __restrict__ b1,
        float* __restrict__ C, int K, int N)
{
    extern __shared__ char smc[];
    const uint32_t sb = smem_u32(smc);
    const int tid = threadIdx.x, lane = tid & 31, wid = tid >> 5;
    const int m0 = blockIdx.y * BM, n0 = blockIdx.x * BN;
    const int wm = (wid & 1) * 64, wn = (wid >> 1) * 32;

    float acc[4][4][4];
#pragma unroll
    for (int i = 0; i < 4; i++)
#pragma unroll
        for (int j = 0; j < 4; j++)
#pragma unroll
            for (int l = 0; l < 4; l++) acc[i][j][l] = 0.0f;

    const int NS = K / BK;

    // loader: per matrix 1024 16B-chunks (128 rows x 8); 4 chunks/thread/matrix
    auto load_stage = [&](int st, int ck) {
        uint32_t sbase = sb + st * STGB;
#pragma unroll
        for (int l = 0; l < 4; l++) {
            int c = tid + l * 256;           // 0..1023
            int row = c >> 3, ch = c & 7;
            uint32_t doff = row * ROWB + ch * 16;
            const __nv_bfloat16* gsrc;
            gsrc = Ahi + (size_t)(m0 + row) * K + ck * BK + ch * 8;
            cpasync16(sbase + 0*MATB + doff, gsrc);
            gsrc = Alo + (size_t)(m0 + row) * K + ck * BK + ch * 8;
            cpasync16(sbase + 1*MATB + doff, gsrc);
            gsrc = Whi + (size_t)(n0 + row) * K + ck * BK + ch * 8;
            cpasync16(sbase + 2*MATB + doff, gsrc);
            gsrc = Wlo + (size_t)(n0 + row) * K + ck * BK + ch * 8;
            cpasync16(sbase + 3*MATB + doff, gsrc);
        }
        cp_commit();
    };

    load_stage(0, 0);

    const uint32_t aoff = (uint32_t)((wm + (lane & 15)) * ROWB + (lane >> 4) * 16);
    const uint32_t boff = (uint32_t)((wn + (lane & 7) + ((lane >> 4) << 3)) * ROWB
                                     + ((lane >> 3) & 1) * 16);

    for (int ck = 0; ck < NS; ck++) {
        const int st = ck & 1;
        if (ck + 1 < NS) {
            load_stage(st ^ 1, ck + 1);
            asm volatile("cp.async.wait_group 1;" ::: "memory");
        } else {
            asm volatile("cp.async.wait_group 0;" ::: "memory");
        }
        __syncthreads();

        const uint32_t sbase = sb + st * STGB;
#pragma unroll
        for (int kk = 0; kk < 4; kk++) {
            const uint32_t ko = kk * 32;
            uint32_t bh[2][4], bl[2][4];
#pragma unroll
            for (int nb = 0; nb < 2; nb++) {
                uint32_t ba = sbase + boff + nb * (16 * ROWB) + ko;
                ldsm4(bh[nb][0], bh[nb][1], bh[nb][2], bh[nb][3], ba + 2*MATB);
                ldsm4(bl[nb][0], bl[nb][1], bl[nb][2], bl[nb][3], ba + 3*MATB);
            }
            uint32_t ah[4][4], al[4][4];
#pragma unroll
            for (int mi = 0; mi < 4; mi++) {
                uint32_t aa = sbase + aoff + mi * (16 * ROWB) + ko;
                ldsm4(ah[mi][0], ah[mi][1], ah[mi][2], ah[mi][3], aa);
                ldsm4(al[mi][0], al[mi][1], al[mi][2], al[mi][3], aa + MATB);
            }
#pragma unroll
            for (int mi = 0; mi < 4; mi++) {
#pragma unroll
                for (int ni = 0; ni < 4; ni++) {
                    const int nb = ni >> 1, pr = (ni & 1) * 2;
                    float* c = acc[mi][ni];
                    mma16816(c, ah[mi][0], ah[mi][1], ah[mi][2], ah[mi][3],
                             bh[nb][pr], bh[nb][pr + 1]);
                    mma16816(c, ah[mi][0], ah[mi][1], ah[mi][2], ah[mi][3],
                             bl[nb][pr], bl[nb][pr + 1]);
                    mma16816(c, al[mi][0], al[mi][1], al[mi][2], al[mi][3],
                             bh[nb][pr], bh[nb][pr + 1]);
                }
            }
        }
        __syncthreads();
    }

#pragma unroll
    for (int ni = 0; ni < 4; ni++) {
        int cc = n0 + wn + ni * 8 + (lane & 3) * 2;
        float bb0 = __ldg(b0 + cc) + (b1 ? __ldg(b1 + cc) : 0.0f);
        float bb1 = __ldg(b0 + cc + 1) + (b1 ? __ldg(b1 + cc + 1) : 0.0f);
#pragma unroll
        for (int mi = 0; mi < 4; mi++) {
            int rr = m0 + wm + mi * 16 + (lane >> 2);
            float* c = acc[mi][ni];
            *(float2*)(C + (size_t)rr * N + cc) =
                make_float2(c[0] + bb0, c[1] + bb1);
            *(float2*)(C + (size_t)(rr + 8) * N + cc) =
                make_float2(c[2] + bb0, c[3] + bb1);
        }
    }
}

// ---------------------------------------------------------------------------
extern "C" void kernel_launch(void* const* d_in, const int* in_sizes, int n_in,
                              void* d_out, int out_size)
{
    const float* x    = (const float*)d_in[0];
    const float* Wih0 = (const float*)d_in[1];
    const float* Whh0 = (const float*)d_in[2];
    const float* bih0 = (const float*)d_in[3];
    const float* bhh0 = (const float*)d_in[4];
    const float* Wih1 = (const float*)d_in[5];
    const float* Whh1 = (const float*)d_in[6];
    const float* bih1 = (const float*)d_in[7];
    const float* bhh1 = (const float*)d_in[8];
    const float* Wout = (const float*)d_in[9];
    const float* bout = (const float*)d_in[10];
    float* out = (float*)d_out;

    float* pre;
    __nv_bfloat16 *ahi, *alo, *whi, *wlo, *shi, *slo, *hhi, *hlo;
    cudaGetSymbolAddress((void**)&pre, g_pre);
    cudaGetSymbolAddress((void**)&ahi, g_ahi);
    cudaGetSymbolAddress((void**)&alo, g_alo);
    cudaGetSymbolAddress((void**)&whi, g_whi);
    cudaGetSymbolAddress((void**)&wlo, g_wlo);
    cudaGetSymbolAddress((void**)&shi, g_shi);
    cudaGetSymbolAddress((void**)&slo, g_slo);
    cudaGetSymbolAddress((void**)&hhi, g_hhi);
    cudaGetSymbolAddress((void**)&hlo, g_hlo);

    cudaFuncSetAttribute(lstm_recur, cudaFuncAttributeMaxDynamicSharedMemorySize,
                         SMEM_RECUR);
    cudaFuncSetAttribute(gemm_tc, cudaFuncAttributeMaxDynamicSharedMemorySize,
                         SMEM_GEMM);

    // ---- Layer 0 ----
    cvt_split<<<(TBn*In/4 + 255)/256, 256>>>(x, ahi, alo, TBn*In/4);
    cvt_split<<<(Gn*In/4 + 255)/256, 256>>>(Wih0, whi, wlo, Gn*In/4);
    gemm_tc<<<dim3(Gn/BN, TBn/BM), 256, SMEM_GEMM>>>(
        ahi, alo, whi, wlo, bih0, bhh0, pre, In, Gn);
    cudaMemsetAsync(hhi, 0, sizeof(__nv_bfloat16)*Bn*Hn);
    cudaMemsetAsync(hlo, 0, sizeof(__nv_bfloat16)*Bn*Hn);
    lstm_recur<<<NCTA, NTHR, SMEM_RECUR>>>(Whh0, pre, shi, slo);

    // ---- Layer 1 (A = hseq hi/lo directly) ----
    cvt_split<<<(Gn*Hn/4 + 255)/256, 256>>>(Wih1, whi, wlo, Gn*Hn/4);
    gemm_tc<<<dim3(Gn/BN, TBn/BM), 256, SMEM_GEMM>>>(
        shi, slo, whi, wlo, bih1, bhh1, pre, Hn, Gn);
    cudaMemsetAsync(hhi, 0, sizeof(__nv_bfloat16)*Bn*Hn);
    cudaMemsetAsync(hlo, 0, sizeof(__nv_bfloat16)*Bn*Hn);
    lstm_recur<<<NCTA, NTHR, SMEM_RECUR>>>(Whh1, pre, shi, slo);

    // ---- Output projection (A = hseq hi/lo) ----
    cvt_split<<<(On*Hn/4 + 255)/256, 256>>>(Wout, whi, wlo, On*Hn/4);
    gemm_tc<<<dim3(On/BN, TBn/BM), 256, SMEM_GEMM>>>(
        shi, slo, whi, wlo, bout, nullptr, out, Hn, On);
}